// round 7
// baseline (speedup 1.0000x reference)
#include <cuda_runtime.h>
#include <cfloat>
#include <cstdint>

// Problem constants
#define S_LEN   2048
#define BATCH   2
#define HDIM    4096
#define NHEADS  32
#define HEADD   128
#define M_ROWS  4096            // B*S
#define QKV_N   12288           // 3*H
#define INV_NORM 0.08838834764831845f   // 1/sqrt(128)

// Scratch (allocation-free rule: __device__ globals)
__device__ float g_qkv[(size_t)M_ROWS * QKV_N];   // 201 MB
__device__ float g_ctx[(size_t)M_ROWS * HDIM];    // 67 MB
__device__ float g_rw [(size_t)QKV_N * HDIM];     // 201 MB (rounded qkv_w)
__device__ float g_rhs[(size_t)M_ROWS * HDIM];    // 67 MB (rounded hs)
__device__ float g_rw2[(size_t)HDIM * HDIM];      // 67 MB (rounded dense_w)
__device__ int   g_all_int01;
__device__ int   g_all_f01;

// ---------------------------------------------------------------------------
__global__ void k_set_flags() { g_all_int01 = 1; g_all_f01 = 1; }

__global__ void k_detect(const int* __restrict__ w, int n) {
    for (int i = blockIdx.x * blockDim.x + threadIdx.x; i < n;
         i += gridDim.x * blockDim.x) {
        int v = w[i];
        if ((unsigned)v > 1u) g_all_int01 = 0;
        float f = __int_as_float(v);
        if (!(f == 0.0f || f == 1.0f)) g_all_f01 = 0;
    }
}

__device__ __forceinline__ uint32_t f2tf32(float x) {
    uint32_t r;
    asm("cvt.rna.tf32.f32 %0, %1;" : "=r"(r) : "f"(x));
    return r;
}
__device__ __forceinline__ float rndf(float x) {
    return __uint_as_float(f2tf32(x));
}

__global__ void k_round(const float4* __restrict__ in, float4* __restrict__ out,
                        int n4) {
    for (int i = blockIdx.x * blockDim.x + threadIdx.x; i < n4;
         i += gridDim.x * blockDim.x) {
        float4 v = in[i];
        v.x = rndf(v.x); v.y = rndf(v.y); v.z = rndf(v.z); v.w = rndf(v.w);
        out[i] = v;
    }
}

// ---------------------------------------------------------------------------
// cp.async helpers
// ---------------------------------------------------------------------------
__device__ __forceinline__ void cp16(void* dst, const void* src) {
    uint32_t d = (uint32_t)__cvta_generic_to_shared(dst);
    asm volatile("cp.async.cg.shared.global [%0], [%1], 16;" :: "r"(d), "l"(src));
}
#define CP_COMMIT()  asm volatile("cp.async.commit_group;")
#define CP_WAIT(n)   asm volatile("cp.async.wait_group %0;" :: "n"(n))

// Operands pre-rounded to tf32; raw bits go straight to the MMA.
#define MMA_TF32(D, a0, a1, a2, a3, b0, b1)                                   \
    asm volatile(                                                             \
        "mma.sync.aligned.m16n8k8.row.col.f32.tf32.tf32.f32 "                 \
        "{%0,%1,%2,%3}, {%4,%5,%6,%7}, {%8,%9}, {%0,%1,%2,%3};"               \
        : "+f"(D[0]), "+f"(D[1]), "+f"(D[2]), "+f"(D[3])                      \
        : "r"(a0), "r"(a1), "r"(a2), "r"(a3), "r"(b0), "r"(b1))

// ---------------------------------------------------------------------------
// TF32 GEMM (NT), 3-stage cp.async pipeline.
// Block 256(M) x 128(N), K-tile 32, 256 threads (8 warps, 4x2),
// warp tile 64x64 -> 1.0 LDS per MMA.
// ---------------------------------------------------------------------------
#define BK 32
#define LDS_PAD 36
#define A_ROWS 256
#define B_ROWS 128
#define ATILE (A_ROWS * LDS_PAD)
#define BTILE (B_ROWS * LDS_PAD)
#define STG_W (ATILE + BTILE)
#define GSTAGES 3
#define GEMM_SMEM_BYTES (GSTAGES * STG_W * 4)

__global__ __launch_bounds__(256, 1)
void gemm_tf32(const float* __restrict__ A, const float* __restrict__ W,
               const float* __restrict__ bias, const float* __restrict__ resid,
               float* __restrict__ C, int M, int N, int K, int round_out)
{
    extern __shared__ uint32_t gsm[];

    const int t    = threadIdx.x;
    const int warp = t >> 5;
    const int lane = t & 31;
    const int gid  = lane >> 2;
    const int tig  = lane & 3;
    const int wm   = (warp >> 1) * 64;   // warp m offset (0,64,128,192)
    const int wn   = (warp & 1) * 64;    // warp n offset (0,64)

    const int bm = blockIdx.y * A_ROWS;
    const int bn = blockIdx.x * B_ROWS;

    float d[4][8][4];
#pragma unroll
    for (int i = 0; i < 4; i++)
#pragma unroll
        for (int j = 0; j < 8; j++)
#pragma unroll
            for (int c = 0; c < 4; c++) d[i][j][c] = 0.f;

    const int NT = K / BK;

    // loader: A 2048 chunks + B 1024 chunks of 16B per stage; 12 per thread
    auto load_stage = [&](int st, int kk0) {
        uint32_t* As = gsm + st * STG_W;
        uint32_t* Ws = As + ATILE;
#pragma unroll
        for (int i = 0; i < 12; i++) {
            const int e = i * 256 + t;
            if (e < 2048) {
                const int r = e >> 3, c4 = (e & 7) << 2;
                cp16(As + r * LDS_PAD + c4, A + (size_t)(bm + r) * K + kk0 + c4);
            } else {
                const int eb = e - 2048;
                const int r = eb >> 3, c4 = (eb & 7) << 2;
                cp16(Ws + r * LDS_PAD + c4, W + (size_t)(bn + r) * K + kk0 + c4);
            }
        }
    };

    load_stage(0, 0);  CP_COMMIT();
    load_stage(1, BK); CP_COMMIT();

    for (int kt = 0; kt < NT; kt++) {
        const int s = kt % GSTAGES;
        CP_WAIT(1);
        __syncthreads();
        if (kt + 2 < NT) load_stage((kt + 2) % GSTAGES, (kt + 2) * BK);
        CP_COMMIT();

        const uint32_t* As = gsm + s * STG_W;
        const uint32_t* Ws = As + ATILE;

#pragma unroll
        for (int kk = 0; kk < BK; kk += 8) {
            uint32_t a[4][4];
#pragma unroll
            for (int mt = 0; mt < 4; mt++) {
                const int r0 = (wm + mt * 16 + gid) * LDS_PAD;
                a[mt][0] = As[r0 + kk + tig];
                a[mt][1] = As[r0 + 8 * LDS_PAD + kk + tig];
                a[mt][2] = As[r0 + kk + tig + 4];
                a[mt][3] = As[r0 + 8 * LDS_PAD + kk + tig + 4];
            }
            uint32_t b[8][2];
#pragma unroll
            for (int nt = 0; nt < 8; nt++) {
                const int r0 = (wn + nt * 8 + gid) * LDS_PAD;
                b[nt][0] = Ws[r0 + kk + tig];
                b[nt][1] = Ws[r0 + kk + tig + 4];
            }
#pragma unroll
            for (int mt = 0; mt < 4; mt++)
#pragma unroll
                for (int nt = 0; nt < 8; nt++)
                    MMA_TF32(d[mt][nt], a[mt][0], a[mt][1], a[mt][2], a[mt][3],
                             b[nt][0], b[nt][1]);
        }
    }

#pragma unroll
    for (int mt = 0; mt < 4; mt++) {
        const int row = bm + wm + mt * 16 + gid;
#pragma unroll
        for (int nt = 0; nt < 8; nt++) {
            const int col = bn + wn + nt * 8 + tig * 2;
            const float b0 = bias[col], b1 = bias[col + 1];
            size_t i0 = (size_t)row * N + col;
            size_t i1 = (size_t)(row + 8) * N + col;
            float2 o0 = make_float2(d[mt][nt][0] + b0, d[mt][nt][1] + b1);
            float2 o1 = make_float2(d[mt][nt][2] + b0, d[mt][nt][3] + b1);
            if (resid) {
                const float2 r0 = *(const float2*)(resid + i0);
                const float2 r1 = *(const float2*)(resid + i1);
                o0.x += r0.x; o0.y += r0.y;
                o1.x += r1.x; o1.y += r1.y;
            }
            if (round_out) {
                o0.x = rndf(o0.x); o0.y = rndf(o0.y);
                o1.x = rndf(o1.x); o1.y = rndf(o1.y);
            }
            *(float2*)(C + i0) = o0;
            *(float2*)(C + i1) = o1;
        }
    }
}

// ---------------------------------------------------------------------------
// Tensor-core flash attention (unchanged from R5 passing version)
// ---------------------------------------------------------------------------
#define BQ 64
#define BKV 64
#define QS 132
#define KS 132
#define VS 136
#define SS 68
#define ATTN_NT (S_LEN / BKV)

#define OFF_SQ   0
#define OFF_SK   (OFF_SQ + 64 * QS)
#define OFF_SV   (OFF_SK + 2 * 64 * KS)
#define OFF_SS   (OFF_SV + 2 * 64 * VS)
#define OFF_RED  (OFF_SS + 64 * SS)
#define OFF_SUM  (OFF_RED + 128)
#define OFF_SM   (OFF_SUM + 128)
#define OFF_SL   (OFF_SM + 64)
#define ATTN_SMEM_BYTES ((OFF_SL + 64) * 4)

__global__ __launch_bounds__(256)
void attn_tc(const float* __restrict__ qkv, const float* __restrict__ alibi,
             const void* __restrict__ maskp, float* __restrict__ ctx)
{
    extern __shared__ uint32_t asm_[];
    uint32_t* sQ   = asm_ + OFF_SQ;
    uint32_t* sK0  = asm_ + OFF_SK;
    uint32_t* sV0  = asm_ + OFF_SV;
    float*    sS   = (float*)(asm_ + OFF_SS);
    float*    sRed = (float*)(asm_ + OFF_RED);
    float*    sSum = (float*)(asm_ + OFF_SUM);
    float*    sM   = (float*)(asm_ + OFF_SM);
    float*    sL   = (float*)(asm_ + OFF_SL);

    const int t    = threadIdx.x;
    const int warp = t >> 5, lane = t & 31;
    const int gid  = lane >> 2, tig = lane & 3;
    const int wr   = warp >> 1, wc = warp & 1;
    const int hh   = blockIdx.y;
    const int b    = hh / NHEADS;
    const int head = hh % NHEADS;
    const int q0   = blockIdx.x * BQ;
    const int mrow = wr * 16 + gid;

    const int mtype = g_all_int01 ? 1 : (g_all_f01 ? 2 : 0);
    const unsigned char* mask_u8 = (const unsigned char*)maskp;
    const int*   mask_i32 = (const int*)maskp;
    const float* mask_f32 = (const float*)maskp;
    const size_t mbase = (size_t)b * S_LEN * S_LEN;

    {
        const float* src = qkv + (size_t)(b * S_LEN + q0) * QKV_N + head * 384;
        for (int e = t; e < BQ * 32; e += 256) {
            int r = e >> 5, d4 = (e & 31) << 2;
            *(float4*)&sQ[r * QS + d4] = *(const float4*)(src + (size_t)r * QKV_N + d4);
        }
    }
    if (t < BQ) { sM[t] = -FLT_MAX; sL[t] = 0.f; }

    const float* kvbase = qkv + (size_t)b * S_LEN * QKV_N + head * 384 + 128;
    auto load_kv = [&](int st, int k0) {
        uint32_t* sK = sK0 + st * 64 * KS;
        uint32_t* sV = sV0 + st * 64 * VS;
#pragma unroll
        for (int e = t; e < BKV * 32; e += 256) {
            int r = e >> 5, d4 = (e & 31) << 2;
            const float* row = kvbase + (size_t)(k0 + r) * QKV_N + d4;
            cp16(sK + r * KS + d4, row);
            cp16(sV + r * VS + d4, row + 128);
        }
    };

    load_kv(0, 0);
    CP_COMMIT();

    float o[8][4];
#pragma unroll
    for (int nt = 0; nt < 8; nt++)
#pragma unroll
        for (int c = 0; c < 4; c++) o[nt][c] = 0.f;

    for (int kt = 0; kt < ATTN_NT; kt++) {
        const int s  = kt & 1;
        const int k0 = kt * BKV;
        CP_WAIT(0);
        __syncthreads();
        if (kt + 1 < ATTN_NT) load_kv(s ^ 1, k0 + BKV);
        CP_COMMIT();

        const uint32_t* sK = sK0 + s * 64 * KS;
        const uint32_t* sV = sV0 + s * 64 * VS;

        float d[4][4];
#pragma unroll
        for (int nt = 0; nt < 4; nt++)
#pragma unroll
            for (int c = 0; c < 4; c++) d[nt][c] = 0.f;

#pragma unroll
        for (int kk = 0; kk < HEADD; kk += 8) {
            const uint32_t a0 = sQ[mrow * QS + kk + tig];
            const uint32_t a1 = sQ[(mrow + 8) * QS + kk + tig];
            const uint32_t a2 = sQ[mrow * QS + kk + tig + 4];
            const uint32_t a3 = sQ[(mrow + 8) * QS + kk + tig + 4];
#pragma unroll
            for (int nt = 0; nt < 4; nt++) {
                const int key = wc * 32 + nt * 8 + gid;
                const uint32_t b0 = sK[key * KS + kk + tig];
                const uint32_t b1 = sK[key * KS + kk + tig + 4];
                MMA_TF32(d[nt], a0, a1, a2, a3, b0, b1);
            }
        }

#pragma unroll
        for (int nt = 0; nt < 4; nt++) {
            const int colL = wc * 32 + nt * 8 + tig * 2;
            const int kc   = k0 + colL;
            const float al0 = alibi[(size_t)hh * S_LEN + kc];
            const float al1 = alibi[(size_t)hh * S_LEN + kc + 1];
            const int qrA = q0 + mrow, qrB = qrA + 8;
            float v00 = al0 + INV_NORM * d[nt][0];
            float v01 = al1 + INV_NORM * d[nt][1];
            float v10 = al0 + INV_NORM * d[nt][2];
            float v11 = al1 + INV_NORM * d[nt][3];
            const size_t mA = mbase + (size_t)qrA * S_LEN + kc;
            const size_t mB = mbase + (size_t)qrB * S_LEN + kc;
            bool k00, k01, k10, k11;
            if (mtype == 1) {
                k00 = mask_i32[mA] != 0;     k01 = mask_i32[mA + 1] != 0;
                k10 = mask_i32[mB] != 0;     k11 = mask_i32[mB + 1] != 0;
            } else if (mtype == 2) {
                k00 = mask_f32[mA] != 0.0f;  k01 = mask_f32[mA + 1] != 0.0f;
                k10 = mask_f32[mB] != 0.0f;  k11 = mask_f32[mB + 1] != 0.0f;
            } else {
                k00 = mask_u8[mA] != 0;      k01 = mask_u8[mA + 1] != 0;
                k10 = mask_u8[mB] != 0;      k11 = mask_u8[mB + 1] != 0;
            }
            d[nt][0] = k00 ? -FLT_MAX : v00;
            d[nt][1] = k01 ? -FLT_MAX : v01;
            d[nt][2] = k10 ? -FLT_MAX : v10;
            d[nt][3] = k11 ? -FLT_MAX : v11;
        }

        float mA = -FLT_MAX, mB = -FLT_MAX;
#pragma unroll
        for (int nt = 0; nt < 4; nt++) {
            mA = fmaxf(mA, fmaxf(d[nt][0], d[nt][1]));
            mB = fmaxf(mB, fmaxf(d[nt][2], d[nt][3]));
        }
        mA = fmaxf(mA, __shfl_xor_sync(0xffffffffu, mA, 1));
        mA = fmaxf(mA, __shfl_xor_sync(0xffffffffu, mA, 2));
        mB = fmaxf(mB, __shfl_xor_sync(0xffffffffu, mB, 1));
        mB = fmaxf(mB, __shfl_xor_sync(0xffffffffu, mB, 2));
        if (tig == 0) {
            sRed[wc * 64 + mrow]     = mA;
            sRed[wc * 64 + mrow + 8] = mB;
        }
        __syncthreads();

        const float moldA = sM[mrow], moldB = sM[mrow + 8];
        const float mnA = fmaxf(moldA, fmaxf(sRed[mrow], sRed[64 + mrow]));
        const float mnB = fmaxf(moldB, fmaxf(sRed[mrow + 8], sRed[64 + mrow + 8]));

        float sumA = 0.f, sumB = 0.f;
#pragma unroll
        for (int nt = 0; nt < 4; nt++) {
            const int colL = wc * 32 + nt * 8 + tig * 2;
            float p00 = __expf(d[nt][0] - mnA);
            float p01 = __expf(d[nt][1] - mnA);
            float p10 = __expf(d[nt][2] - mnB);
            float p11 = __expf(d[nt][3] - mnB);
            sumA += p00 + p01;
            sumB += p10 + p11;
            *(float2*)&sS[mrow * SS + colL] =
                make_float2(rndf(p00), rndf(p01));
            *(float2*)&sS[(mrow + 8) * SS + colL] =
                make_float2(rndf(p10), rndf(p11));
        }
        sumA += __shfl_xor_sync(0xffffffffu, sumA, 1);
        sumA += __shfl_xor_sync(0xffffffffu, sumA, 2);
        sumB += __shfl_xor_sync(0xffffffffu, sumB, 1);
        sumB += __shfl_xor_sync(0xffffffffu, sumB, 2);
        if (tig == 0) {
            sSum[wc * 64 + mrow]     = sumA;
            sSum[wc * 64 + mrow + 8] = sumB;
        }
        const float cA = __expf(moldA - mnA);
        const float cB = __expf(moldB - mnB);
        __syncthreads();

        if (wc == 0 && tig == 0) {
            sM[mrow]     = mnA;
            sM[mrow + 8] = mnB;
            sL[mrow]     = sL[mrow]     * cA + sSum[mrow]     + sSum[64 + mrow];
            sL[mrow + 8] = sL[mrow + 8] * cB + sSum[mrow + 8] + sSum[64 + mrow + 8];
        }

#pragma unroll
        for (int nt = 0; nt < 8; nt++) {
            o[nt][0] *= cA; o[nt][1] *= cA;
            o[nt][2] *= cB; o[nt][3] *= cB;
        }
#pragma unroll
        for (int kk = 0; kk < BKV; kk += 8) {
            const uint32_t a0 = __float_as_uint(sS[mrow * SS + kk + tig]);
            const uint32_t a1 = __float_as_uint(sS[(mrow + 8) * SS + kk + tig]);
            const uint32_t a2 = __float_as_uint(sS[mrow * SS + kk + tig + 4]);
            const uint32_t a3 = __float_as_uint(sS[(mrow + 8) * SS + kk + tig + 4]);
#pragma unroll
            for (int nt = 0; nt < 8; nt++) {
                const int col = wc * 64 + nt * 8 + gid;
                const uint32_t b0 = sV[(kk + tig) * VS + col];
                const uint32_t b1 = sV[(kk + tig + 4) * VS + col];
                MMA_TF32(o[nt], a0, a1, a2, a3, b0, b1);
            }
        }
    }

    __syncthreads();
    {
        const float lA = 1.0f / sL[mrow];
        const float lB = 1.0f / sL[mrow + 8];
        const int rowA = b * S_LEN + q0 + mrow;
#pragma unroll
        for (int nt = 0; nt < 8; nt++) {
            const int col = head * HEADD + wc * 64 + nt * 8 + tig * 2;
            *(float2*)&ctx[(size_t)rowA * HDIM + col] =
                make_float2(rndf(o[nt][0] * lA), rndf(o[nt][1] * lA));
            *(float2*)&ctx[(size_t)(rowA + 8) * HDIM + col] =
                make_float2(rndf(o[nt][2] * lB), rndf(o[nt][3] * lB));
        }
    }
}

// ---------------------------------------------------------------------------
extern "C" void kernel_launch(void* const* d_in, const int* in_sizes, int n_in,
                              void* d_out, int out_size)
{
    const float* hs    = (const float*)d_in[0];
    const float* resid = (const float*)d_in[1];
    const float* alibi = (const float*)d_in[2];
    const void*  maskp = d_in[3];
    const float* qkv_w = (const float*)d_in[4];
    const float* qkv_b = (const float*)d_in[5];
    const float* dw    = (const float*)d_in[6];
    const float* db    = (const float*)d_in[7];
    float* out = (float*)d_out;

    float *qkv_buf, *ctx_buf, *rw_buf, *rhs_buf, *rw2_buf;
    cudaGetSymbolAddress((void**)&qkv_buf, g_qkv);
    cudaGetSymbolAddress((void**)&ctx_buf, g_ctx);
    cudaGetSymbolAddress((void**)&rw_buf,  g_rw);
    cudaGetSymbolAddress((void**)&rhs_buf, g_rhs);
    cudaGetSymbolAddress((void**)&rw2_buf, g_rw2);

    cudaFuncSetAttribute(gemm_tf32, cudaFuncAttributeMaxDynamicSharedMemorySize,
                         GEMM_SMEM_BYTES);
    cudaFuncSetAttribute(attn_tc, cudaFuncAttributeMaxDynamicSharedMemorySize,
                         ATTN_SMEM_BYTES);

    // launches 0-4 (so ncu -s 5 profiles gemm1)
    k_set_flags<<<1, 1>>>();
    k_detect<<<256, 256>>>((const int*)maskp, in_sizes[3] / 4);
    k_round<<<4096, 256>>>((const float4*)qkv_w, (float4*)rw_buf,
                           (int)((size_t)QKV_N * HDIM / 4));
    k_round<<<2048, 256>>>((const float4*)hs, (float4*)rhs_buf,
                           (int)((size_t)M_ROWS * HDIM / 4));
    k_round<<<2048, 256>>>((const float4*)dw, (float4*)rw2_buf,
                           (int)((size_t)HDIM * HDIM / 4));

    // QKV projection (outputs rounded to tf32 for attention)
    gemm_tf32<<<dim3(QKV_N / B_ROWS, M_ROWS / A_ROWS), 256, GEMM_SMEM_BYTES>>>(
        rhs_buf, rw_buf, qkv_b, nullptr, qkv_buf, M_ROWS, QKV_N, HDIM, 1);

    // Flash attention -> g_ctx (rounded at store)
    attn_tc<<<dim3(S_LEN / BQ, BATCH * NHEADS), 256, ATTN_SMEM_BYTES>>>(
        qkv_buf, alibi, maskp, ctx_buf);

    // Output projection + bias + residual -> d_out
    gemm_tf32<<<dim3(HDIM / B_ROWS, M_ROWS / A_ROWS), 256, GEMM_SMEM_BYTES>>>(
        ctx_buf, rw2_buf, db, resid, out, M_ROWS, HDIM, HDIM, 0);
}

// round 8
// speedup vs baseline: 1.8696x; 1.8696x over previous
#include <cuda_runtime.h>
#include <cuda_fp16.h>
#include <cfloat>
#include <cstdint>

// Problem constants
#define S_LEN   2048
#define BATCH   2
#define HDIM    4096
#define NHEADS  32
#define HEADD   128
#define M_ROWS  4096            // B*S
#define QKV_N   12288           // 3*H
#define INV_NORM 0.08838834764831845f   // 1/sqrt(128)

// Scratch (allocation-free rule: __device__ globals). All half-precision.
__device__ __half g_qkvh[(size_t)M_ROWS * 8192];        // [row][head][{q,k}][128]
__device__ __half g_vth [(size_t)64 * 128 * 2048];      // [b*NH+h][d][s] (V^T)
__device__ __half g_rwh [(size_t)QKV_N * HDIM];         // qkv_w half
__device__ __half g_rhsh[(size_t)M_ROWS * HDIM];        // hs half
__device__ __half g_rw2h[(size_t)HDIM * HDIM];          // dense_w half
__device__ __half g_ctxh[(size_t)M_ROWS * HDIM];        // ctx half
__device__ int   g_all_int01;
__device__ int   g_all_f01;

// ---------------------------------------------------------------------------
__global__ void k_set_flags() { g_all_int01 = 1; g_all_f01 = 1; }

__global__ void k_detect(const int* __restrict__ w, int n) {
    for (int i = blockIdx.x * blockDim.x + threadIdx.x; i < n;
         i += gridDim.x * blockDim.x) {
        int v = w[i];
        if ((unsigned)v > 1u) g_all_int01 = 0;
        float f = __int_as_float(v);
        if (!(f == 0.0f || f == 1.0f)) g_all_f01 = 0;
    }
}

// f32 -> packed half2 conversion pass
__global__ void k_cvt(const float4* __restrict__ in, uint2* __restrict__ out,
                      int n4) {
    for (int i = blockIdx.x * blockDim.x + threadIdx.x; i < n4;
         i += gridDim.x * blockDim.x) {
        float4 v = in[i];
        __half2 lo = __float22half2_rn(make_float2(v.x, v.y));
        __half2 hi = __float22half2_rn(make_float2(v.z, v.w));
        uint2 o;
        o.x = *(uint32_t*)&lo;
        o.y = *(uint32_t*)&hi;
        out[i] = o;
    }
}

// ---------------------------------------------------------------------------
// cp.async helpers
// ---------------------------------------------------------------------------
__device__ __forceinline__ void cp16(void* dst, const void* src) {
    uint32_t d = (uint32_t)__cvta_generic_to_shared(dst);
    asm volatile("cp.async.cg.shared.global [%0], [%1], 16;" :: "r"(d), "l"(src));
}
#define CP_COMMIT()  asm volatile("cp.async.commit_group;")
#define CP_WAIT(n)   asm volatile("cp.async.wait_group %0;" :: "n"(n))

// fp16 MMA m16n8k16, f32 accumulate
#define MMA_F16(D, a0, a1, a2, a3, b0, b1)                                    \
    asm volatile(                                                             \
        "mma.sync.aligned.m16n8k16.row.col.f32.f16.f16.f32 "                  \
        "{%0,%1,%2,%3}, {%4,%5,%6,%7}, {%8,%9}, {%0,%1,%2,%3};"               \
        : "+f"(D[0]), "+f"(D[1]), "+f"(D[2]), "+f"(D[3])                      \
        : "r"(a0), "r"(a1), "r"(a2), "r"(a3), "r"(b0), "r"(b1))

// ---------------------------------------------------------------------------
// FP16 GEMM (NT), 3-stage cp.async pipeline.
// Block 128x128, K-tile 32 halves, 256 threads (8 warps 4x2), warp tile 32x64.
// Smem rows: 32 halves (64B) padded to 80B (20 uint32) -> conflict-free frags.
// mode 0: f32 out C = acc + bias + resid
// mode 1: qkv split -> g_qkvh (q,k packed half) + g_vth (V transposed half)
// ---------------------------------------------------------------------------
#define GBK 32                       // K-tile in halves
#define GPAD 20                      // row stride in uint32 (80B)
#define GROWB 80                     // row stride bytes
#define GSTG_B (256 * GROWB)         // 20480 B per stage (A 128 rows + B 128)
#define GNSTG 3
#define GEMM_SMEM_BYTES (GNSTG * GSTG_B)

__global__ __launch_bounds__(256, 2)
void gemm_f16(const __half* __restrict__ A, const __half* __restrict__ W,
              const float* __restrict__ bias, const float* __restrict__ resid,
              float* __restrict__ C, int M, int N, int K, int mode)
{
    extern __shared__ unsigned char gsmb[];

    const int t    = threadIdx.x;
    const int warp = t >> 5;
    const int lane = t & 31;
    const int gid  = lane >> 2;
    const int tig  = lane & 3;
    const int wm   = (warp >> 1) * 32;
    const int wn   = (warp & 1) * 64;

    const int bm = blockIdx.y * 128;
    const int bn = blockIdx.x * 128;
    const int NT = K / GBK;

    float d[2][8][4];
#pragma unroll
    for (int i = 0; i < 2; i++)
#pragma unroll
        for (int j = 0; j < 8; j++)
#pragma unroll
            for (int c = 0; c < 4; c++) d[i][j][c] = 0.f;

    // loader: 256 rows x 4 chunks (16B) = 1024 tasks, 4 per thread
    auto load_stage = [&](int st, int kk0) {
        unsigned char* stg = gsmb + st * GSTG_B;
#pragma unroll
        for (int i = 0; i < 4; i++) {
            const int e = i * 256 + t;
            const int r = e >> 2, c = e & 3;
            const __half* src = (r < 128)
                ? A + (size_t)(bm + r) * K + kk0 + c * 8
                : W + (size_t)(bn + r - 128) * K + kk0 + c * 8;
            cp16(stg + r * GROWB + c * 16, src);
        }
    };

    load_stage(0, 0);    CP_COMMIT();
    load_stage(1, GBK);  CP_COMMIT();

    for (int kt = 0; kt < NT; kt++) {
        const int s = kt % GNSTG;
        CP_WAIT(1);
        __syncthreads();
        if (kt + 2 < NT) load_stage((kt + 2) % GNSTG, (kt + 2) * GBK);
        CP_COMMIT();

        const uint32_t* As = (const uint32_t*)(gsmb + s * GSTG_B);
        const uint32_t* Ws = As + 128 * GPAD;

#pragma unroll
        for (int ks = 0; ks < 2; ks++) {
            uint32_t a[2][4];
#pragma unroll
            for (int mt = 0; mt < 2; mt++) {
                const int r = wm + mt * 16 + gid;
                a[mt][0] = As[r * GPAD + ks * 8 + tig];
                a[mt][1] = As[(r + 8) * GPAD + ks * 8 + tig];
                a[mt][2] = As[r * GPAD + ks * 8 + 4 + tig];
                a[mt][3] = As[(r + 8) * GPAD + ks * 8 + 4 + tig];
            }
            uint32_t b[8][2];
#pragma unroll
            for (int nt = 0; nt < 8; nt++) {
                const int r = wn + nt * 8 + gid;
                b[nt][0] = Ws[r * GPAD + ks * 8 + tig];
                b[nt][1] = Ws[r * GPAD + ks * 8 + 4 + tig];
            }
#pragma unroll
            for (int mt = 0; mt < 2; mt++)
#pragma unroll
                for (int nt = 0; nt < 8; nt++)
                    MMA_F16(d[mt][nt], a[mt][0], a[mt][1], a[mt][2], a[mt][3],
                            b[nt][0], b[nt][1]);
        }
    }

    // Epilogue
#pragma unroll
    for (int mt = 0; mt < 2; mt++) {
        const int r0 = bm + wm + mt * 16 + gid;
#pragma unroll
        for (int nt = 0; nt < 8; nt++) {
            const int col = bn + wn + nt * 8 + tig * 2;
            const float b0 = bias[col], b1 = bias[col + 1];
            float v00 = d[mt][nt][0] + b0, v01 = d[mt][nt][1] + b1;
            float v10 = d[mt][nt][2] + b0, v11 = d[mt][nt][3] + b1;
            if (mode == 0) {
                size_t i0 = (size_t)r0 * N + col;
                size_t i1 = (size_t)(r0 + 8) * N + col;
                const float2 rr0 = *(const float2*)(resid + i0);
                const float2 rr1 = *(const float2*)(resid + i1);
                *(float2*)(C + i0) = make_float2(v00 + rr0.x, v01 + rr0.y);
                *(float2*)(C + i1) = make_float2(v10 + rr1.x, v11 + rr1.y);
            } else {
                const int head = col / 384;
                const int rem  = col - head * 384;
                const int part = rem >> 7;
                const int dd   = rem & 127;
                if (part < 2) {
                    size_t base = (size_t)r0 * 8192 + head * 256 + part * 128 + dd;
                    *(__half2*)&g_qkvh[base] =
                        __float22half2_rn(make_float2(v00, v01));
                    *(__half2*)&g_qkvh[base + (size_t)8 * 8192] =
                        __float22half2_rn(make_float2(v10, v11));
                } else {
                    const int bb = r0 >> 11, s0 = r0 & 2047;
                    size_t vb = ((size_t)(bb * 32 + head) * 128 + dd) * 2048;
                    g_vth[vb + s0]            = __float2half_rn(v00);
                    g_vth[vb + 2048 + s0]     = __float2half_rn(v01);
                    g_vth[vb + s0 + 8]        = __float2half_rn(v10);
                    g_vth[vb + 2048 + s0 + 8] = __float2half_rn(v11);
                }
            }
        }
    }
}

// ---------------------------------------------------------------------------
// FP16 flash attention, double-buffered K/V via cp.async, 2 CTAs/SM.
// Q,K: [row][64 k-pairs] stride 68 u32; V^T: [d][32 key-pairs] stride 36 u32;
// P: [row][32 pairs] stride 36 u32. All fragment LDS conflict-free.
// ---------------------------------------------------------------------------
#define BQ 64
#define BKV 64
#define ATTN_NT (S_LEN / BKV)
#define QROWB 272                    // 68 u32
#define VROWB 144                    // 36 u32
#define SROWB 144                    // 36 u32

#define SQ_OFF  0
#define SK_OFF  (SQ_OFF + 64 * QROWB)            // 2 stages of 64*272
#define SVT_OFF (SK_OFF + 2 * 64 * QROWB)        // 2 stages of 128*144
#define SS_OFF  (SVT_OFF + 2 * 128 * VROWB)
#define RED_OFF (SS_OFF + 64 * SROWB)            // floats: 2x64 + 2x64 + 64 + 64
#define ATTN_SMEM_BYTES (RED_OFF + 384 * 4)

__global__ __launch_bounds__(256, 2)
void attn_f16(const float* __restrict__ alibi, const void* __restrict__ maskp,
              __half* __restrict__ ctx)
{
    extern __shared__ unsigned char smem[];
    float* sRed = (float*)(smem + RED_OFF);        // 2 x 64
    float* sSum = sRed + 128;                      // 2 x 64
    float* sM   = sSum + 128;                      // 64
    float* sL   = sM + 64;                         // 64

    const int t    = threadIdx.x;
    const int warp = t >> 5, lane = t & 31;
    const int gid  = lane >> 2, tig = lane & 3;
    const int wr   = warp >> 1, wc = warp & 1;
    const int hh   = blockIdx.y;
    const int b    = hh / NHEADS;
    const int head = hh % NHEADS;
    const int q0   = blockIdx.x * BQ;
    const int mrow = wr * 16 + gid;

    const int mtype = g_all_int01 ? 1 : (g_all_f01 ? 2 : 0);
    const unsigned char* mask_u8 = (const unsigned char*)maskp;
    const int*   mask_i32 = (const int*)maskp;
    const float* mask_f32 = (const float*)maskp;
    const size_t mbase = (size_t)b * S_LEN * S_LEN;

    // Q tile: 64 rows x 16 chunks (256B of halves per row)
    {
        const __half* qsrc = g_qkvh + (size_t)(b * S_LEN + q0) * 8192 + head * 256;
        for (int e = t; e < 1024; e += 256) {
            const int r = e >> 4, c = e & 15;
            cp16(smem + SQ_OFF + r * QROWB + c * 16, qsrc + (size_t)r * 8192 + c * 8);
        }
    }
    if (t < BQ) { sM[t] = -FLT_MAX; sL[t] = 0.f; }

    const __half* ksrc0 = g_qkvh + (size_t)b * S_LEN * 8192 + head * 256 + 128;
    const __half* vsrc0 = g_vth + (size_t)hh * 128 * 2048;

    auto load_kv = [&](int st, int k0) {
        unsigned char* sK = smem + SK_OFF + st * (64 * QROWB);
        unsigned char* sV = smem + SVT_OFF + st * (128 * VROWB);
        for (int e = t; e < 2048; e += 256) {
            if (e < 1024) {   // K: 64 rows x 16 chunks
                const int r = e >> 4, c = e & 15;
                cp16(sK + r * QROWB + c * 16,
                     ksrc0 + (size_t)(k0 + r) * 8192 + c * 8);
            } else {          // V^T: 128 d-rows x 8 chunks (128B per row)
                const int e2 = e - 1024;
                const int r = e2 >> 3, c = e2 & 7;
                cp16(sV + r * VROWB + c * 16,
                     vsrc0 + (size_t)r * 2048 + k0 + c * 8);
            }
        }
    };

    load_kv(0, 0);
    CP_COMMIT();

    float o[8][4];
#pragma unroll
    for (int nt = 0; nt < 8; nt++)
#pragma unroll
        for (int c = 0; c < 4; c++) o[nt][c] = 0.f;

    for (int kt = 0; kt < ATTN_NT; kt++) {
        const int s  = kt & 1;
        const int k0 = kt * BKV;
        CP_WAIT(0);
        __syncthreads();                          // sync1
        if (kt + 1 < ATTN_NT) load_kv(s ^ 1, k0 + BKV);
        CP_COMMIT();

        const uint32_t* Qp = (const uint32_t*)(smem + SQ_OFF);
        const uint32_t* Kp = (const uint32_t*)(smem + SK_OFF + s * (64 * QROWB));
        const uint32_t* Vp = (const uint32_t*)(smem + SVT_OFF + s * (128 * VROWB));
        uint32_t*       Sp = (uint32_t*)(smem + SS_OFF);

        // Phase 1: S = Q K^T (fp16 k16 steps)
        float d[4][4];
#pragma unroll
        for (int nt = 0; nt < 4; nt++)
#pragma unroll
            for (int c = 0; c < 4; c++) d[nt][c] = 0.f;

#pragma unroll
        for (int ks = 0; ks < 8; ks++) {
            const uint32_t a0 = Qp[mrow * 68 + ks * 8 + tig];
            const uint32_t a1 = Qp[(mrow + 8) * 68 + ks * 8 + tig];
            const uint32_t a2 = Qp[mrow * 68 + ks * 8 + 4 + tig];
            const uint32_t a3 = Qp[(mrow + 8) * 68 + ks * 8 + 4 + tig];
#pragma unroll
            for (int nt = 0; nt < 4; nt++) {
                const int key = wc * 32 + nt * 8 + gid;
                const uint32_t b0 = Kp[key * 68 + ks * 8 + tig];
                const uint32_t b1 = Kp[key * 68 + ks * 8 + 4 + tig];
                MMA_F16(d[nt], a0, a1, a2, a3, b0, b1);
            }
        }

        // alibi + mask in registers
#pragma unroll
        for (int nt = 0; nt < 4; nt++) {
            const int colL = wc * 32 + nt * 8 + tig * 2;
            const int kc   = k0 + colL;
            const float al0 = alibi[(size_t)hh * S_LEN + kc];
            const float al1 = alibi[(size_t)hh * S_LEN + kc + 1];
            const int qrA = q0 + mrow, qrB = qrA + 8;
            float v00 = al0 + INV_NORM * d[nt][0];
            float v01 = al1 + INV_NORM * d[nt][1];
            float v10 = al0 + INV_NORM * d[nt][2];
            float v11 = al1 + INV_NORM * d[nt][3];
            const size_t mA = mbase + (size_t)qrA * S_LEN + kc;
            const size_t mB = mbase + (size_t)qrB * S_LEN + kc;
            bool k00, k01, k10, k11;
            if (mtype == 1) {
                k00 = mask_i32[mA] != 0;     k01 = mask_i32[mA + 1] != 0;
                k10 = mask_i32[mB] != 0;     k11 = mask_i32[mB + 1] != 0;
            } else if (mtype == 2) {
                k00 = mask_f32[mA] != 0.0f;  k01 = mask_f32[mA + 1] != 0.0f;
                k10 = mask_f32[mB] != 0.0f;  k11 = mask_f32[mB + 1] != 0.0f;
            } else {
                k00 = mask_u8[mA] != 0;      k01 = mask_u8[mA + 1] != 0;
                k10 = mask_u8[mB] != 0;      k11 = mask_u8[mB + 1] != 0;
            }
            d[nt][0] = k00 ? -FLT_MAX : v00;
            d[nt][1] = k01 ? -FLT_MAX : v01;
            d[nt][2] = k10 ? -FLT_MAX : v10;
            d[nt][3] = k11 ? -FLT_MAX : v11;
        }

        // row max via quad shuffle + cross-warp exchange
        float mA = -FLT_MAX, mB = -FLT_MAX;
#pragma unroll
        for (int nt = 0; nt < 4; nt++) {
            mA = fmaxf(mA, fmaxf(d[nt][0], d[nt][1]));
            mB = fmaxf(mB, fmaxf(d[nt][2], d[nt][3]));
        }
        mA = fmaxf(mA, __shfl_xor_sync(0xffffffffu, mA, 1));
        mA = fmaxf(mA, __shfl_xor_sync(0xffffffffu, mA, 2));
        mB = fmaxf(mB, __shfl_xor_sync(0xffffffffu, mB, 1));
        mB = fmaxf(mB, __shfl_xor_sync(0xffffffffu, mB, 2));
        if (tig == 0) {
            sRed[wc * 64 + mrow]     = mA;
            sRed[wc * 64 + mrow + 8] = mB;
        }
        __syncthreads();                          // sync2

        const float moldA = sM[mrow], moldB = sM[mrow + 8];
        const float mnA = fmaxf(moldA, fmaxf(sRed[mrow], sRed[64 + mrow]));
        const float mnB = fmaxf(moldB, fmaxf(sRed[mrow + 8], sRed[64 + mrow + 8]));

        float sumA = 0.f, sumB = 0.f;
#pragma unroll
        for (int nt = 0; nt < 4; nt++) {
            float p00 = __expf(d[nt][0] - mnA);
            float p01 = __expf(d[nt][1] - mnA);
            float p10 = __expf(d[nt][2] - mnB);
            float p11 = __expf(d[nt][3] - mnB);
            sumA += p00 + p01;
            sumB += p10 + p11;
            const int pi = wc * 16 + nt * 4 + tig;   // pair index
            __half2 hA = __float22half2_rn(make_float2(p00, p01));
            __half2 hB = __float22half2_rn(make_float2(p10, p11));
            Sp[mrow * 36 + pi]       = *(uint32_t*)&hA;
            Sp[(mrow + 8) * 36 + pi] = *(uint32_t*)&hB;
        }
        sumA += __shfl_xor_sync(0xffffffffu, sumA, 1);
        sumA += __shfl_xor_sync(0xffffffffu, sumA, 2);
        sumB += __shfl_xor_sync(0xffffffffu, sumB, 1);
        sumB += __shfl_xor_sync(0xffffffffu, sumB, 2);
        if (tig == 0) {
            sSum[wc * 64 + mrow]     = sumA;
            sSum[wc * 64 + mrow + 8] = sumB;
        }
        const float cA = __expf(moldA - mnA);
        const float cB = __expf(moldB - mnB);
        __syncthreads();                          // sync3

        if (wc == 0 && tig == 0) {
            sM[mrow]     = mnA;
            sM[mrow + 8] = mnB;
            sL[mrow]     = sL[mrow]     * cA + sSum[mrow]     + sSum[64 + mrow];
            sL[mrow + 8] = sL[mrow + 8] * cB + sSum[mrow + 8] + sSum[64 + mrow + 8];
        }

        // Phase 3: O = O*c + P @ V (fp16 k16, V^T natural layout)
#pragma unroll
        for (int nt = 0; nt < 8; nt++) {
            o[nt][0] *= cA; o[nt][1] *= cA;
            o[nt][2] *= cB; o[nt][3] *= cB;
        }
#pragma unroll
        for (int ks = 0; ks < 4; ks++) {
            const uint32_t a0 = Sp[mrow * 36 + ks * 8 + tig];
            const uint32_t a1 = Sp[(mrow + 8) * 36 + ks * 8 + tig];
            const uint32_t a2 = Sp[mrow * 36 + ks * 8 + 4 + tig];
            const uint32_t a3 = Sp[(mrow + 8) * 36 + ks * 8 + 4 + tig];
#pragma unroll
            for (int nt = 0; nt < 8; nt++) {
                const int colD = wc * 64 + nt * 8 + gid;
                const uint32_t b0 = Vp[colD * 36 + ks * 8 + tig];
                const uint32_t b1 = Vp[colD * 36 + ks * 8 + 4 + tig];
                MMA_F16(o[nt], a0, a1, a2, a3, b0, b1);
            }
        }
    }

    __syncthreads();
    {
        const float lA = 1.0f / sL[mrow];
        const float lB = 1.0f / sL[mrow + 8];
        const int rowA = b * S_LEN + q0 + mrow;
#pragma unroll
        for (int nt = 0; nt < 8; nt++) {
            const int col = head * HEADD + wc * 64 + nt * 8 + tig * 2;
            *(__half2*)&ctx[(size_t)rowA * HDIM + col] =
                __float22half2_rn(make_float2(o[nt][0] * lA, o[nt][1] * lA));
            *(__half2*)&ctx[(size_t)(rowA + 8) * HDIM + col] =
                __float22half2_rn(make_float2(o[nt][2] * lB, o[nt][3] * lB));
        }
    }
}

// ---------------------------------------------------------------------------
extern "C" void kernel_launch(void* const* d_in, const int* in_sizes, int n_in,
                              void* d_out, int out_size)
{
    const float* hs    = (const float*)d_in[0];
    const float* resid = (const float*)d_in[1];
    const float* alibi = (const float*)d_in[2];
    const void*  maskp = d_in[3];
    const float* qkv_w = (const float*)d_in[4];
    const float* qkv_b = (const float*)d_in[5];
    const float* dw    = (const float*)d_in[6];
    const float* db    = (const float*)d_in[7];
    float* out = (float*)d_out;

    __half *rw, *rhs, *rw2, *ctxh;
    cudaGetSymbolAddress((void**)&rw,   g_rwh);
    cudaGetSymbolAddress((void**)&rhs,  g_rhsh);
    cudaGetSymbolAddress((void**)&rw2,  g_rw2h);
    cudaGetSymbolAddress((void**)&ctxh, g_ctxh);

    cudaFuncSetAttribute(gemm_f16, cudaFuncAttributeMaxDynamicSharedMemorySize,
                         GEMM_SMEM_BYTES);
    cudaFuncSetAttribute(attn_f16, cudaFuncAttributeMaxDynamicSharedMemorySize,
                         ATTN_SMEM_BYTES);

    k_set_flags<<<1, 1>>>();
    k_detect<<<256, 256>>>((const int*)maskp, in_sizes[3] / 4);

    // f32 -> half converts (rne)
    k_cvt<<<4096, 256>>>((const float4*)qkv_w, (uint2*)rw,
                         (int)((size_t)QKV_N * HDIM / 4));
    k_cvt<<<2048, 256>>>((const float4*)hs, (uint2*)rhs,
                         (int)((size_t)M_ROWS * HDIM / 4));
    k_cvt<<<2048, 256>>>((const float4*)dw, (uint2*)rw2,
                         (int)((size_t)HDIM * HDIM / 4));

    // QKV projection (fp16 tensor cores) -> g_qkvh (q,k) + g_vth (V^T)
    gemm_f16<<<dim3(QKV_N / 128, M_ROWS / 128), 256, GEMM_SMEM_BYTES>>>(
        rhs, rw, qkv_b, nullptr, nullptr, M_ROWS, QKV_N, HDIM, 1);

    // Flash attention (fp16 tensor cores) -> g_ctxh
    attn_f16<<<dim3(S_LEN / BQ, BATCH * NHEADS), 256, ATTN_SMEM_BYTES>>>(
        alibi, maskp, ctxh);

    // Output projection + bias + residual (fp16 tensor cores, f32 out)
    gemm_f16<<<dim3(HDIM / 128, M_ROWS / 128), 256, GEMM_SMEM_BYTES>>>(
        ctxh, rw2, db, resid, out, M_ROWS, HDIM, HDIM, 0);
}

// round 9
// speedup vs baseline: 2.2508x; 1.2039x over previous
#include <cuda_runtime.h>
#include <cuda_fp16.h>
#include <cfloat>
#include <cstdint>

// Problem constants
#define S_LEN   2048
#define BATCH   2
#define HDIM    4096
#define NHEADS  32
#define HEADD   128
#define M_ROWS  4096            // B*S
#define QKV_N   12288           // 3*H
#define INV_NORM 0.08838834764831845f   // 1/sqrt(128)

// Scratch (allocation-free rule: __device__ globals). All half-precision.
__device__ __half g_qkvh[(size_t)M_ROWS * 8192];        // [row][head][{q,k}][128]
__device__ __half g_vth [(size_t)64 * 128 * 2048];      // [b*NH+h][d][s] (V^T)
__device__ __half g_rwh [(size_t)QKV_N * HDIM];         // qkv_w half
__device__ __half g_rhsh[(size_t)M_ROWS * HDIM];        // hs half
__device__ __half g_rw2h[(size_t)HDIM * HDIM];          // dense_w half
__device__ __half g_ctxh[(size_t)M_ROWS * HDIM];        // ctx half
__device__ unsigned char g_mask8[(size_t)BATCH * S_LEN * S_LEN];  // packed mask
__device__ int   g_all_int01;
__device__ int   g_all_f01;

// ---------------------------------------------------------------------------
__global__ void k_set_flags() { g_all_int01 = 1; g_all_f01 = 1; }

__global__ void k_detect(const int* __restrict__ w, int n) {
    for (int i = blockIdx.x * blockDim.x + threadIdx.x; i < n;
         i += gridDim.x * blockDim.x) {
        int v = w[i];
        if ((unsigned)v > 1u) g_all_int01 = 0;
        float f = __int_as_float(v);
        if (!(f == 0.0f || f == 1.0f)) g_all_f01 = 0;
    }
}

// Pack mask (any wire dtype) -> u8 0/1
__global__ void k_pack(const void* __restrict__ in,
                       unsigned char* __restrict__ out, int n4) {
    const int mtype = g_all_int01 ? 1 : (g_all_f01 ? 2 : 0);
    for (int i = blockIdx.x * blockDim.x + threadIdx.x; i < n4;
         i += gridDim.x * blockDim.x) {
        uchar4 o;
        if (mtype == 1) {
            int4 v = ((const int4*)in)[i];
            o = make_uchar4(v.x != 0, v.y != 0, v.z != 0, v.w != 0);
        } else if (mtype == 2) {
            float4 v = ((const float4*)in)[i];
            o = make_uchar4(v.x != 0.f, v.y != 0.f, v.z != 0.f, v.w != 0.f);
        } else {
            uchar4 v = ((const uchar4*)in)[i];
            o = make_uchar4(v.x != 0, v.y != 0, v.z != 0, v.w != 0);
        }
        ((uchar4*)out)[i] = o;
    }
}

// f32 -> packed half2 conversion pass
__global__ void k_cvt(const float4* __restrict__ in, uint2* __restrict__ out,
                      int n4) {
    for (int i = blockIdx.x * blockDim.x + threadIdx.x; i < n4;
         i += gridDim.x * blockDim.x) {
        float4 v = in[i];
        __half2 lo = __float22half2_rn(make_float2(v.x, v.y));
        __half2 hi = __float22half2_rn(make_float2(v.z, v.w));
        uint2 o;
        o.x = *(uint32_t*)&lo;
        o.y = *(uint32_t*)&hi;
        out[i] = o;
    }
}

// ---------------------------------------------------------------------------
// cp.async helpers
// ---------------------------------------------------------------------------
__device__ __forceinline__ void cp16(void* dst, const void* src) {
    uint32_t d = (uint32_t)__cvta_generic_to_shared(dst);
    asm volatile("cp.async.cg.shared.global [%0], [%1], 16;" :: "r"(d), "l"(src));
}
#define CP_COMMIT()  asm volatile("cp.async.commit_group;")
#define CP_WAIT(n)   asm volatile("cp.async.wait_group %0;" :: "n"(n))

// fp16 MMA m16n8k16, f32 accumulate
#define MMA_F16(D, a0, a1, a2, a3, b0, b1)                                    \
    asm volatile(                                                             \
        "mma.sync.aligned.m16n8k16.row.col.f32.f16.f16.f32 "                  \
        "{%0,%1,%2,%3}, {%4,%5,%6,%7}, {%8,%9}, {%0,%1,%2,%3};"               \
        : "+f"(D[0]), "+f"(D[1]), "+f"(D[2]), "+f"(D[3])                      \
        : "r"(a0), "r"(a1), "r"(a2), "r"(a3), "r"(b0), "r"(b1))

// pair barrier: warps 2p and 2p+1 (64 threads), named id p+1 (0 is CTA-wide)
#define BARP(p) asm volatile("bar.sync %0, 64;" :: "r"((p) + 1) : "memory")

// ---------------------------------------------------------------------------
// FP16 GEMM (NT), 3-stage cp.async pipeline.
// Block 128x128, K-tile 64 halves, 256 threads (8 warps 4x2), warp tile 32x64.
// Smem rows: 64 halves (128B) padded to 144B (36 u32) -> conflict-free frags.
// mode 0: f32 out C = acc + bias + resid
// mode 1: qkv split -> g_qkvh (q,k packed half) + g_vth (V transposed half)
// ---------------------------------------------------------------------------
#define GBK 64                       // K-tile in halves
#define GPAD 36                      // row stride in uint32 (144B)
#define GROWB 144                    // row stride bytes
#define GSTG_B (256 * GROWB)         // 36864 B per stage (A 128 rows + B 128)
#define GNSTG 3
#define GEMM_SMEM_BYTES (GNSTG * GSTG_B)

__global__ __launch_bounds__(256, 2)
void gemm_f16(const __half* __restrict__ A, const __half* __restrict__ W,
              const float* __restrict__ bias, const float* __restrict__ resid,
              float* __restrict__ C, int M, int N, int K, int mode)
{
    extern __shared__ unsigned char gsmb[];

    const int t    = threadIdx.x;
    const int warp = t >> 5;
    const int lane = t & 31;
    const int gid  = lane >> 2;
    const int tig  = lane & 3;
    const int wm   = (warp >> 1) * 32;
    const int wn   = (warp & 1) * 64;

    const int bm = blockIdx.y * 128;
    const int bn = blockIdx.x * 128;
    const int NT = K / GBK;

    float d[2][8][4];
#pragma unroll
    for (int i = 0; i < 2; i++)
#pragma unroll
        for (int j = 0; j < 8; j++)
#pragma unroll
            for (int c = 0; c < 4; c++) d[i][j][c] = 0.f;

    // loader: 256 rows x 8 chunks (16B) = 2048 tasks, 8 per thread
    auto load_stage = [&](int st, int kk0) {
        unsigned char* stg = gsmb + st * GSTG_B;
#pragma unroll
        for (int i = 0; i < 8; i++) {
            const int e = i * 256 + t;
            const int r = e >> 3, c = e & 7;
            const __half* src = (r < 128)
                ? A + (size_t)(bm + r) * K + kk0 + c * 8
                : W + (size_t)(bn + r - 128) * K + kk0 + c * 8;
            cp16(stg + r * GROWB + c * 16, src);
        }
    };

    load_stage(0, 0);    CP_COMMIT();
    load_stage(1, GBK);  CP_COMMIT();

    for (int kt = 0; kt < NT; kt++) {
        const int s = kt % GNSTG;
        CP_WAIT(1);
        __syncthreads();
        if (kt + 2 < NT) load_stage((kt + 2) % GNSTG, (kt + 2) * GBK);
        CP_COMMIT();

        const uint32_t* As = (const uint32_t*)(gsmb + s * GSTG_B);
        const uint32_t* Ws = As + 128 * GPAD;

#pragma unroll
        for (int ks = 0; ks < 4; ks++) {
            uint32_t a[2][4];
#pragma unroll
            for (int mt = 0; mt < 2; mt++) {
                const int r = wm + mt * 16 + gid;
                a[mt][0] = As[r * GPAD + ks * 8 + tig];
                a[mt][1] = As[(r + 8) * GPAD + ks * 8 + tig];
                a[mt][2] = As[r * GPAD + ks * 8 + 4 + tig];
                a[mt][3] = As[(r + 8) * GPAD + ks * 8 + 4 + tig];
            }
            uint32_t b[8][2];
#pragma unroll
            for (int nt = 0; nt < 8; nt++) {
                const int r = wn + nt * 8 + gid;
                b[nt][0] = Ws[r * GPAD + ks * 8 + tig];
                b[nt][1] = Ws[r * GPAD + ks * 8 + 4 + tig];
            }
#pragma unroll
            for (int mt = 0; mt < 2; mt++)
#pragma unroll
                for (int nt = 0; nt < 8; nt++)
                    MMA_F16(d[mt][nt], a[mt][0], a[mt][1], a[mt][2], a[mt][3],
                            b[nt][0], b[nt][1]);
        }
    }

    // Epilogue
#pragma unroll
    for (int mt = 0; mt < 2; mt++) {
        const int r0 = bm + wm + mt * 16 + gid;
#pragma unroll
        for (int nt = 0; nt < 8; nt++) {
            const int col = bn + wn + nt * 8 + tig * 2;
            const float b0 = bias[col], b1 = bias[col + 1];
            float v00 = d[mt][nt][0] + b0, v01 = d[mt][nt][1] + b1;
            float v10 = d[mt][nt][2] + b0, v11 = d[mt][nt][3] + b1;
            if (mode == 0) {
                size_t i0 = (size_t)r0 * N + col;
                size_t i1 = (size_t)(r0 + 8) * N + col;
                const float2 rr0 = *(const float2*)(resid + i0);
                const float2 rr1 = *(const float2*)(resid + i1);
                *(float2*)(C + i0) = make_float2(v00 + rr0.x, v01 + rr0.y);
                *(float2*)(C + i1) = make_float2(v10 + rr1.x, v11 + rr1.y);
            } else {
                const int head = col / 384;
                const int rem  = col - head * 384;
                const int part = rem >> 7;
                const int dd   = rem & 127;
                if (part < 2) {
                    size_t base = (size_t)r0 * 8192 + head * 256 + part * 128 + dd;
                    *(__half2*)&g_qkvh[base] =
                        __float22half2_rn(make_float2(v00, v01));
                    *(__half2*)&g_qkvh[base + (size_t)8 * 8192] =
                        __float22half2_rn(make_float2(v10, v11));
                } else {
                    const int bb = r0 >> 11, s0 = r0 & 2047;
                    size_t vb = ((size_t)(bb * 32 + head) * 128 + dd) * 2048;
                    g_vth[vb + s0]            = __float2half_rn(v00);
                    g_vth[vb + 2048 + s0]     = __float2half_rn(v01);
                    g_vth[vb + s0 + 8]        = __float2half_rn(v10);
                    g_vth[vb + 2048 + s0 + 8] = __float2half_rn(v11);
                }
            }
        }
    }
}

// ---------------------------------------------------------------------------
// FP16 flash attention, double-buffered K/V via cp.async, 2 CTAs/SM.
// Softmax m/l state in registers (per-wc partial l); pair barriers for the
// max exchange and P visibility; u8 packed mask.
// ---------------------------------------------------------------------------
#define BQ 64
#define BKV 64
#define ATTN_NT (S_LEN / BKV)
#define QROWB 272                    // 68 u32
#define VROWB 144                    // 36 u32
#define SROWB 144                    // 36 u32

#define SQ_OFF  0
#define SK_OFF  (SQ_OFF + 64 * QROWB)            // 2 stages of 64*272
#define SVT_OFF (SK_OFF + 2 * 64 * QROWB)        // 2 stages of 128*144
#define SS_OFF  (SVT_OFF + 2 * 128 * VROWB)
#define RED_OFF (SS_OFF + 64 * SROWB)            // 128 floats (4 pairs x 32)
#define ATTN_SMEM_BYTES (RED_OFF + 128 * 4)

__global__ __launch_bounds__(256, 2)
void attn_f16(const float* __restrict__ alibi,
              const unsigned char* __restrict__ mask8,
              __half* __restrict__ ctx)
{
    extern __shared__ unsigned char smem[];
    float* sRed = (float*)(smem + RED_OFF);

    const int t    = threadIdx.x;
    const int warp = t >> 5, lane = t & 31;
    const int gid  = lane >> 2, tig = lane & 3;
    const int wr   = warp >> 1, wc = warp & 1;
    const int hh   = blockIdx.y;
    const int b    = hh / NHEADS;
    const int head = hh % NHEADS;
    const int q0   = blockIdx.x * BQ;
    const int mrow = wr * 16 + gid;
    const int redW = wr * 32 + wc * 16 + gid;         // own slot
    const int redO = wr * 32 + (1 - wc) * 16 + gid;   // partner slot

    const size_t mbase = (size_t)b * S_LEN * S_LEN;

    // Q tile: 64 rows x 16 chunks (256B of halves per row)
    {
        const __half* qsrc = g_qkvh + (size_t)(b * S_LEN + q0) * 8192 + head * 256;
        for (int e = t; e < 1024; e += 256) {
            const int r = e >> 4, c = e & 15;
            cp16(smem + SQ_OFF + r * QROWB + c * 16, qsrc + (size_t)r * 8192 + c * 8);
        }
    }

    const __half* ksrc0 = g_qkvh + (size_t)b * S_LEN * 8192 + head * 256 + 128;
    const __half* vsrc0 = g_vth + (size_t)hh * 128 * 2048;

    auto load_kv = [&](int st, int k0) {
        unsigned char* sK = smem + SK_OFF + st * (64 * QROWB);
        unsigned char* sV = smem + SVT_OFF + st * (128 * VROWB);
        for (int e = t; e < 2048; e += 256) {
            if (e < 1024) {   // K: 64 rows x 16 chunks
                const int r = e >> 4, c = e & 15;
                cp16(sK + r * QROWB + c * 16,
                     ksrc0 + (size_t)(k0 + r) * 8192 + c * 8);
            } else {          // V^T: 128 d-rows x 8 chunks (128B per row)
                const int e2 = e - 1024;
                const int r = e2 >> 3, c = e2 & 7;
                cp16(sV + r * VROWB + c * 16,
                     vsrc0 + (size_t)r * 2048 + k0 + c * 8);
            }
        }
    };

    load_kv(0, 0);
    CP_COMMIT();

    float o[8][4];
#pragma unroll
    for (int nt = 0; nt < 8; nt++)
#pragma unroll
        for (int c = 0; c < 4; c++) o[nt][c] = 0.f;

    // softmax state in registers (rows mrow / mrow+8; l is wc-partial)
    float stMA = -FLT_MAX, stMB = -FLT_MAX;
    float stLA = 0.f, stLB = 0.f;

    for (int kt = 0; kt < ATTN_NT; kt++) {
        const int s  = kt & 1;
        const int k0 = kt * BKV;
        CP_WAIT(0);
        __syncthreads();                          // buffers rotated
        if (kt + 1 < ATTN_NT) load_kv(s ^ 1, k0 + BKV);
        CP_COMMIT();

        const uint32_t* Qp = (const uint32_t*)(smem + SQ_OFF);
        const uint32_t* Kp = (const uint32_t*)(smem + SK_OFF + s * (64 * QROWB));
        const uint32_t* Vp = (const uint32_t*)(smem + SVT_OFF + s * (128 * VROWB));
        uint32_t*       Sp = (uint32_t*)(smem + SS_OFF);

        // Phase 1: S = Q K^T (fp16 k16 steps)
        float d[4][4];
#pragma unroll
        for (int nt = 0; nt < 4; nt++)
#pragma unroll
            for (int c = 0; c < 4; c++) d[nt][c] = 0.f;

#pragma unroll
        for (int ks = 0; ks < 8; ks++) {
            const uint32_t a0 = Qp[mrow * 68 + ks * 8 + tig];
            const uint32_t a1 = Qp[(mrow + 8) * 68 + ks * 8 + tig];
            const uint32_t a2 = Qp[mrow * 68 + ks * 8 + 4 + tig];
            const uint32_t a3 = Qp[(mrow + 8) * 68 + ks * 8 + 4 + tig];
#pragma unroll
            for (int nt = 0; nt < 4; nt++) {
                const int key = wc * 32 + nt * 8 + gid;
                const uint32_t b0 = Kp[key * 68 + ks * 8 + tig];
                const uint32_t b1 = Kp[key * 68 + ks * 8 + 4 + tig];
                MMA_F16(d[nt], a0, a1, a2, a3, b0, b1);
            }
        }

        // alibi + packed-u8 mask in registers
#pragma unroll
        for (int nt = 0; nt < 4; nt++) {
            const int colL = wc * 32 + nt * 8 + tig * 2;
            const int kc   = k0 + colL;
            const float2 al = *(const float2*)(alibi + (size_t)hh * S_LEN + kc);
            const int qrA = q0 + mrow, qrB = qrA + 8;
            const uchar2 m0 = *(const uchar2*)(mask8 + mbase + (size_t)qrA * S_LEN + kc);
            const uchar2 m1 = *(const uchar2*)(mask8 + mbase + (size_t)qrB * S_LEN + kc);
            d[nt][0] = m0.x ? -FLT_MAX : al.x + INV_NORM * d[nt][0];
            d[nt][1] = m0.y ? -FLT_MAX : al.y + INV_NORM * d[nt][1];
            d[nt][2] = m1.x ? -FLT_MAX : al.x + INV_NORM * d[nt][2];
            d[nt][3] = m1.y ? -FLT_MAX : al.y + INV_NORM * d[nt][3];
        }

        // partial row max (this wc's 32 cols) via quad shuffle
        float mAp = -FLT_MAX, mBp = -FLT_MAX;
#pragma unroll
        for (int nt = 0; nt < 4; nt++) {
            mAp = fmaxf(mAp, fmaxf(d[nt][0], d[nt][1]));
            mBp = fmaxf(mBp, fmaxf(d[nt][2], d[nt][3]));
        }
        mAp = fmaxf(mAp, __shfl_xor_sync(0xffffffffu, mAp, 1));
        mAp = fmaxf(mAp, __shfl_xor_sync(0xffffffffu, mAp, 2));
        mBp = fmaxf(mBp, __shfl_xor_sync(0xffffffffu, mBp, 1));
        mBp = fmaxf(mBp, __shfl_xor_sync(0xffffffffu, mBp, 2));
        if (tig == 0) {
            sRed[redW]     = mAp;
            sRed[redW + 8] = mBp;
        }
        BARP(wr);                                 // max exchange within pair

        const float mnA = fmaxf(stMA, fmaxf(mAp, sRed[redO]));
        const float mnB = fmaxf(stMB, fmaxf(mBp, sRed[redO + 8]));
        const float cA = __expf(stMA - mnA);
        const float cB = __expf(stMB - mnB);
        stMA = mnA; stMB = mnB;

        float sumA = 0.f, sumB = 0.f;
#pragma unroll
        for (int nt = 0; nt < 4; nt++) {
            float p00 = __expf(d[nt][0] - mnA);
            float p01 = __expf(d[nt][1] - mnA);
            float p10 = __expf(d[nt][2] - mnB);
            float p11 = __expf(d[nt][3] - mnB);
            sumA += p00 + p01;
            sumB += p10 + p11;
            const int pi = wc * 16 + nt * 4 + tig;   // pair index
            __half2 hA = __float22half2_rn(make_float2(p00, p01));
            __half2 hB = __float22half2_rn(make_float2(p10, p11));
            Sp[mrow * 36 + pi]       = *(uint32_t*)&hA;
            Sp[(mrow + 8) * 36 + pi] = *(uint32_t*)&hB;
        }
        sumA += __shfl_xor_sync(0xffffffffu, sumA, 1);
        sumA += __shfl_xor_sync(0xffffffffu, sumA, 2);
        sumB += __shfl_xor_sync(0xffffffffu, sumB, 1);
        sumB += __shfl_xor_sync(0xffffffffu, sumB, 2);
        stLA = stLA * cA + sumA;                  // wc-partial l
        stLB = stLB * cB + sumB;
        BARP(wr);                                 // P visible within pair

        // Phase 3: O = O*c + P @ V (fp16 k16, V^T natural layout)
#pragma unroll
        for (int nt = 0; nt < 8; nt++) {
            o[nt][0] *= cA; o[nt][1] *= cA;
            o[nt][2] *= cB; o[nt][3] *= cB;
        }
#pragma unroll
        for (int ks = 0; ks < 4; ks++) {
            const uint32_t a0 = Sp[mrow * 36 + ks * 8 + tig];
            const uint32_t a1 = Sp[(mrow + 8) * 36 + ks * 8 + tig];
            const uint32_t a2 = Sp[mrow * 36 + ks * 8 + 4 + tig];
            const uint32_t a3 = Sp[(mrow + 8) * 36 + ks * 8 + 4 + tig];
#pragma unroll
            for (int nt = 0; nt < 8; nt++) {
                const int colD = wc * 64 + nt * 8 + gid;
                const uint32_t b0 = Vp[colD * 36 + ks * 8 + tig];
                const uint32_t b1 = Vp[colD * 36 + ks * 8 + 4 + tig];
                MMA_F16(o[nt], a0, a1, a2, a3, b0, b1);
            }
        }
    }

    // epilogue: merge the two wc-partial l's, divide, store
    if (tig == 0) {
        sRed[redW]     = stLA;
        sRed[redW + 8] = stLB;
    }
    BARP(wr);
    {
        const float lA = 1.0f / (stLA + sRed[redO]);
        const float lB = 1.0f / (stLB + sRed[redO + 8]);
        const int rowA = b * S_LEN + q0 + mrow;
#pragma unroll
        for (int nt = 0; nt < 8; nt++) {
            const int col = head * HEADD + wc * 64 + nt * 8 + tig * 2;
            *(__half2*)&ctx[(size_t)rowA * HDIM + col] =
                __float22half2_rn(make_float2(o[nt][0] * lA, o[nt][1] * lA));
            *(__half2*)&ctx[(size_t)(rowA + 8) * HDIM + col] =
                __float22half2_rn(make_float2(o[nt][2] * lB, o[nt][3] * lB));
        }
    }
}

// ---------------------------------------------------------------------------
extern "C" void kernel_launch(void* const* d_in, const int* in_sizes, int n_in,
                              void* d_out, int out_size)
{
    const float* hs    = (const float*)d_in[0];
    const float* resid = (const float*)d_in[1];
    const float* alibi = (const float*)d_in[2];
    const void*  maskp = d_in[3];
    const float* qkv_w = (const float*)d_in[4];
    const float* qkv_b = (const float*)d_in[5];
    const float* dw    = (const float*)d_in[6];
    const float* db    = (const float*)d_in[7];
    float* out = (float*)d_out;

    __half *rw, *rhs, *rw2, *ctxh;
    unsigned char* mask8;
    cudaGetSymbolAddress((void**)&rw,    g_rwh);
    cudaGetSymbolAddress((void**)&rhs,   g_rhsh);
    cudaGetSymbolAddress((void**)&rw2,   g_rw2h);
    cudaGetSymbolAddress((void**)&ctxh,  g_ctxh);
    cudaGetSymbolAddress((void**)&mask8, g_mask8);

    cudaFuncSetAttribute(gemm_f16, cudaFuncAttributeMaxDynamicSharedMemorySize,
                         GEMM_SMEM_BYTES);
    cudaFuncSetAttribute(attn_f16, cudaFuncAttributeMaxDynamicSharedMemorySize,
                         ATTN_SMEM_BYTES);

    k_set_flags<<<1, 1>>>();
    k_detect<<<256, 256>>>((const int*)maskp, in_sizes[3] / 4);
    k_pack<<<1024, 256>>>(maskp, mask8, in_sizes[3] / 4);

    // f32 -> half converts (rne)
    k_cvt<<<4096, 256>>>((const float4*)qkv_w, (uint2*)rw,
                         (int)((size_t)QKV_N * HDIM / 4));
    k_cvt<<<2048, 256>>>((const float4*)hs, (uint2*)rhs,
                         (int)((size_t)M_ROWS * HDIM / 4));
    k_cvt<<<2048, 256>>>((const float4*)dw, (uint2*)rw2,
                         (int)((size_t)HDIM * HDIM / 4));

    // QKV projection (fp16 tensor cores) -> g_qkvh (q,k) + g_vth (V^T)
    gemm_f16<<<dim3(QKV_N / 128, M_ROWS / 128), 256, GEMM_SMEM_BYTES>>>(
        rhs, rw, qkv_b, nullptr, nullptr, M_ROWS, QKV_N, HDIM, 1);

    // Flash attention (fp16 tensor cores) -> g_ctxh
    attn_f16<<<dim3(S_LEN / BQ, BATCH * NHEADS), 256, ATTN_SMEM_BYTES>>>(
        alibi, mask8, ctxh);

    // Output projection + bias + residual (fp16 tensor cores, f32 out)
    gemm_f16<<<dim3(HDIM / 128, M_ROWS / 128), 256, GEMM_SMEM_BYTES>>>(
        ctxh, rw2, db, resid, out, M_ROWS, HDIM, HDIM, 0);
}